// round 12
// baseline (speedup 1.0000x reference)
#include <cuda_runtime.h>
#include <cuda_fp16.h>
#include <cstdint>
#include <math.h>

#define Dm    192
#define ROWSn 16      // batch rows per CTA -> 32 tokens
#define NTH   256     // 8 warps; 2 CTAs per SM
#define SD    194     // fp32 stride (floats): even (float2 align), %32==2
#define SDH   200     // fp16 192-wide stride (halves): 400B%128==16 (LDSM clean)
#define SHD   392     // fp16 384-wide stride (halves): 784B%128==16
#define WTS2  200     // weight tile stride (halves)
#define TILE192 (64 * WTS2)   // 12800 halves per 64x192 k-chunk tile

// smem offsets (floats)
#define OFB    0       // sB fp32 master [32][SD]                  (6208)
#define OFP0   6208    // P0: q/ctx | hidden lo | cls-out          (3200)
#define OFP1   9408    // P1: k     | hidden hi | cls-out tail     (3200)
#define OFP2   12608   // P2: input/v | x-shadow -> z              (3200)
#define OFW    15808   // weight slots 2 x TILE192                 (12800)
#define OFMISC 28608   // softmax weights 3*64                     (192)
#define SMEM_FLOATS 28800
#define SMEM_BYTES  (SMEM_FLOATS * 4)   // 115200 B; 2 CTAs/SM

// ---------------- fp16 k-major weight buffers ----------------
__device__ __align__(16) __half g_hWp[192 * 192];
__device__ __align__(16) __half g_hWt[192 * 192];
__device__ __align__(16) __half g_hQp[192 * 576];   // (in_w @ Wp)^T k-major
__device__ __align__(16) __half g_hQt[192 * 576];   // (in_w @ Wt)^T k-major
__device__ __align__(16) __half g_hOut[192 * 192];
__device__ __align__(16) __half g_hF1[192 * 384];
__device__ __align__(16) __half g_hF2[384 * 192];
__device__ __align__(16) __half g_hC1[192 * 192];
__device__ __align__(16) __half g_hFp2[192 * 192];  // fp_w padded to 192 cols
__device__ float g_bQp[576];
__device__ float g_bQt[576];

__device__ __forceinline__ void cp_async16(uint32_t dst, const void* src) {
    asm volatile("cp.async.cg.shared.global [%0], [%1], 16;\n" :: "r"(dst), "l"(src));
}

// Prep: k-major fp16 transposes, fp_w zero-pad, and algebraic fusion of the
// input projections into the QKV weights/biases (fp32 math, rounded once).
__global__ void prep_kernel(const float* Wp, const float* Wt, const float* in_w,
                            const float* in_b, const float* bp, const float* bt,
                            const float* out_w, const float* f1w, const float* f2w,
                            const float* c1w, const float* fpw) {
    const int t0 = blockIdx.x * blockDim.x + threadIdx.x;
    const int nthr = gridDim.x * blockDim.x;
    {
        const float* srcs[6] = {Wp, Wt, out_w, f1w, f2w, c1w};
        __half* dsts[6] = {g_hWp, g_hWt, g_hOut, g_hF1, g_hF2, g_hC1};
        const int Rs[6] = {192, 192, 192, 384, 192, 192};
        const int Cs[6] = {192, 192, 192, 192, 384, 192};
#pragma unroll 1
        for (int m = 0; m < 6; ++m) {
            int n = Rs[m] * Cs[m];
            for (int d = t0; d < n; d += nthr) {
                int k = d / Rs[m], j = d % Rs[m];
                dsts[m][d] = __float2half(srcs[m][j * Cs[m] + k]);
            }
        }
    }
    for (int d = t0; d < 192 * 192; d += nthr) {
        int k = d / 192, j = d % 192;
        g_hFp2[d] = __float2half(j < 128 ? fpw[j * 192 + k] : 0.f);
    }
    for (int d = t0; d < 192 * 576; d += nthr) {
        int k = d / 576, j = d % 576;
        float sp = 0.f, st = 0.f;
        const float* iw = in_w + (size_t)j * 192;
#pragma unroll 4
        for (int m = 0; m < 192; ++m) {
            float w = iw[m];
            sp += w * Wp[m * 192 + k];
            st += w * Wt[m * 192 + k];
        }
        g_hQp[d] = __float2half(sp);
        g_hQt[d] = __float2half(st);
    }
    for (int j = t0; j < 576; j += nthr) {
        float sp = in_b[j], st = in_b[j];
        const float* iw = in_w + (size_t)j * 192;
#pragma unroll 4
        for (int m = 0; m < 192; ++m) {
            float w = iw[m];
            sp += w * bp[m];
            st += w * bt[m];
        }
        g_bQp[j] = sp;
        g_bQt[j] = st;
    }
}

#define MMA16(dd, a0, a1, a2, a3, b0, b1)                                        \
    asm volatile("mma.sync.aligned.m16n8k16.row.col.f32.f16.f16.f32 "            \
                 "{%0,%1,%2,%3}, {%4,%5,%6,%7}, {%8,%9}, {%0,%1,%2,%3};"         \
                 : "+f"(dd[0]), "+f"(dd[1]), "+f"(dd[2]), "+f"(dd[3])            \
                 : "r"(a0), "r"(a1), "r"(a2), "r"(a3), "r"(b0), "r"(b1))

// ---------------- fp16 GEMM pass, M=32, N=192 ----------------
// out[r][j] (+)= sum_k A[r][k] * W[k][jw0+j], k = nk*64 chunks.
// 8 warps: mblk=wid&1 (m16), nblk=wid>>1 (n48). Per k16: 1 A-LDSM, 3 B-LDSM, 6 MMA.
// Weight slots: 2. Non-dual: alternating slots, prefetch ch+1 after the chunk
// barrier. Dual (gW2): both slots per chunk (slot0=gW rows 0..15, slot1=gW2 rows
// 16..31). preEpiSync: barrier before epilogue (for in-place A overwrite).
__device__ __noinline__ void gemm192(
    const __half* __restrict__ sA, int lda,
    const __half* __restrict__ gW, const __half* __restrict__ gW2,
    int ldw, int jw0, int nk,
    const float* __restrict__ bias, const float* __restrict__ bias2,
    float* __restrict__ outF, int ldoF,
    __half* __restrict__ outH, int ldoH, int jo0,
    bool accOut, bool relu, bool preEpiSync, __half* __restrict__ sW)
{
    const int tid = threadIdx.x;
    const int wid = tid >> 5, lane = tid & 31;
    const int mblk = wid & 1, nblk = wid >> 1;
    const int g = lane >> 2, c = lane & 3;
    const int r0 = mblk * 16;
    const bool dual = (gW2 != nullptr);

    const uint32_t swu = (uint32_t)__cvta_generic_to_shared(sW);
    const uint32_t aAddr0 = (uint32_t)__cvta_generic_to_shared(sA) +
        (uint32_t)(((r0 + (lane & 15)) * lda + ((lane >> 4) << 3)) * 2);
    const int bk = (lane & 7) | (lane & 8);
    const int bn0 = nblk * 48 + ((lane >> 4) << 3);

    __syncthreads();   // prior pass done with weight slots / producers of sA, outF

    auto issue = [&](int ch) {
        uint32_t dbase = swu + (uint32_t)((dual ? 0 : (ch & 1)) * TILE192 * 2);
        const __half* gs = gW + (size_t)(ch * 64) * ldw + jw0;
#pragma unroll
        for (int i = 0; i < 6; ++i) {
            int seg = tid + i * NTH;          // 0..1535
            int row = seg / 24, col = (seg % 24) << 3;
            cp_async16(dbase + (uint32_t)((row * WTS2 + col) * 2),
                       gs + (size_t)row * ldw + col);
        }
        if (dual) {
            const __half* gs2 = gW2 + (size_t)(ch * 64) * ldw + jw0;
#pragma unroll
            for (int i = 0; i < 6; ++i) {
                int seg = tid + i * NTH;
                int row = seg / 24, col = (seg % 24) << 3;
                cp_async16(dbase + (uint32_t)((TILE192 + row * WTS2 + col) * 2),
                           gs2 + (size_t)row * ldw + col);
            }
        }
        asm volatile("cp.async.commit_group;\n" ::: "memory");
    };

    float d[6][4];
#pragma unroll
    for (int nt = 0; nt < 6; ++nt)
        d[nt][0] = d[nt][1] = d[nt][2] = d[nt][3] = 0.f;

    if (!dual) issue(0);

    for (int ch = 0; ch < nk; ++ch) {
        if (dual) {
            if (ch > 0) __syncthreads();   // prior chunk's slot readers done
            issue(ch);
            asm volatile("cp.async.wait_group 0;\n" ::: "memory");
            __syncthreads();
        } else {
            asm volatile("cp.async.wait_group 0;\n" ::: "memory");
            __syncthreads();               // slot (ch&1) visible to all
            if (ch + 1 < nk) issue(ch + 1);   // slot (ch+1)&1 free (read in ch-1)
        }
        if (ch == 0 && accOut) {
            int rA = r0 + g, rB = rA + 8;
#pragma unroll
            for (int nt = 0; nt < 6; ++nt) {
                int jc = nblk * 48 + nt * 8 + 2 * c;
                float2 o0 = *(const float2*)&outF[rA * ldoF + jo0 + jc];
                float2 o1 = *(const float2*)&outF[rB * ldoF + jo0 + jc];
                d[nt][0] += o0.x; d[nt][1] += o0.y;
                d[nt][2] += o1.x; d[nt][3] += o1.y;
            }
        }
        uint32_t wb = swu +
            (uint32_t)(((dual ? mblk : (ch & 1)) * TILE192) * 2);
        uint32_t aAddr = aAddr0 + (uint32_t)(ch * 64 * 2);
#pragma unroll
        for (int ks = 0; ks < 4; ++ks) {
            uint32_t a0, a1, a2, a3;
            asm volatile("ldmatrix.sync.aligned.m8n8.x4.shared.b16 {%0,%1,%2,%3}, [%4];"
                         : "=r"(a0), "=r"(a1), "=r"(a2), "=r"(a3)
                         : "r"(aAddr + (uint32_t)(ks * 16 * 2)));
            uint32_t bBase = wb + (uint32_t)(((ks * 16 + bk) * WTS2 + bn0) * 2);
#pragma unroll
            for (int gi = 0; gi < 3; ++gi) {
                uint32_t b0, b1, b2, b3;
                asm volatile("ldmatrix.sync.aligned.m8n8.x4.trans.shared.b16 "
                             "{%0,%1,%2,%3}, [%4];"
                             : "=r"(b0), "=r"(b1), "=r"(b2), "=r"(b3)
                             : "r"(bBase + (uint32_t)(gi * 16 * 2)));
                MMA16(d[gi * 2],     a0, a1, a2, a3, b0, b1);
                MMA16(d[gi * 2 + 1], a0, a1, a2, a3, b2, b3);
            }
        }
    }

    if (preEpiSync) __syncthreads();   // all A reads done before in-place store

    int rA = r0 + g, rB = rA + 8;
    const float* bptr = (dual && mblk) ? bias2 : bias;
#pragma unroll
    for (int nt = 0; nt < 6; ++nt) {
        int jc = nblk * 48 + nt * 8 + 2 * c;
        float2 v0 = make_float2(d[nt][0], d[nt][1]);
        float2 v1 = make_float2(d[nt][2], d[nt][3]);
        if (bias) {
            float bx = bptr[jw0 + jc], by = bptr[jw0 + jc + 1];
            v0.x += bx; v0.y += by; v1.x += bx; v1.y += by;
        }
        if (relu) {
            v0.x = fmaxf(v0.x, 0.f); v0.y = fmaxf(v0.y, 0.f);
            v1.x = fmaxf(v1.x, 0.f); v1.y = fmaxf(v1.y, 0.f);
        }
        if (outF) {
            *(float2*)&outF[rA * ldoF + jo0 + jc] = v0;
            *(float2*)&outF[rB * ldoF + jo0 + jc] = v1;
        }
        if (outH) {
            *(__half2*)&outH[rA * ldoH + jo0 + jc] = __floats2half2_rn(v0.x, v0.y);
            *(__half2*)&outH[rB * ldoH + jo0 + jc] = __floats2half2_rn(v1.x, v1.y);
        }
    }
}

// ---------------- attention, 3 heads, pairs (r, r+16) ----------------
__device__ __forceinline__ void attention_all(const __half* sQ, const __half* sK,
                                              const __half* sV, __half* ctxH,
                                              float* sMisc) {
    const int tid = threadIdx.x;
    const int wid = tid >> 5, lane = tid & 31;
#pragma unroll
    for (int uu = 0; uu < 6; ++uu) {
        int u = wid * 6 + uu;          // 48 units: 3 heads x 16 pairs
        int h = u >> 4, r = u & 15;
        int t0 = r, t1 = r + 16;
        int col = h * 64 + lane;
        float q0a = __half2float(sQ[t0 * SDH + col]);
        float q0b = __half2float(sQ[t0 * SDH + col + 32]);
        float q1a = __half2float(sQ[t1 * SDH + col]);
        float q1b = __half2float(sQ[t1 * SDH + col + 32]);
        float k0a = __half2float(sK[t0 * SDH + col]);
        float k0b = __half2float(sK[t0 * SDH + col + 32]);
        float k1a = __half2float(sK[t1 * SDH + col]);
        float k1b = __half2float(sK[t1 * SDH + col + 32]);
        float d00 = q0a * k0a + q0b * k0b;
        float d01 = q0a * k1a + q0b * k1b;
        float d10 = q1a * k0a + q1b * k0b;
        float d11 = q1a * k1a + q1b * k1b;
#pragma unroll
        for (int o = 16; o; o >>= 1) {
            d00 += __shfl_xor_sync(0xffffffffu, d00, o);
            d01 += __shfl_xor_sync(0xffffffffu, d01, o);
            d10 += __shfl_xor_sync(0xffffffffu, d10, o);
            d11 += __shfl_xor_sync(0xffffffffu, d11, o);
        }
        if (lane == 0) {
            const float sc = 0.125f;   // 1/sqrt(64)
            d00 *= sc; d01 *= sc; d10 *= sc; d11 *= sc;
            float m0 = fmaxf(d00, d01), m1 = fmaxf(d10, d11);
            float e00 = __expf(d00 - m0), e01 = __expf(d01 - m0);
            float e10 = __expf(d10 - m1), e11 = __expf(d11 - m1);
            float i0 = 1.f / (e00 + e01), i1 = 1.f / (e10 + e11);
            sMisc[h * 64 + t0 * 2 + 0] = e00 * i0;
            sMisc[h * 64 + t0 * 2 + 1] = e01 * i0;
            sMisc[h * 64 + t1 * 2 + 0] = e10 * i1;
            sMisc[h * 64 + t1 * 2 + 1] = e11 * i1;
        }
    }
    __syncthreads();   // scores ready; q reads done -> ctx may overwrite q

#pragma unroll
    for (int e = 0; e < 24; ++e) {
        int idx = tid + e * NTH;       // 0..6143
        int t = idx / 192, j = idx % 192;
        int rr = t & 15, h = j >> 6;
        float w0 = sMisc[h * 64 + t * 2], w1 = sMisc[h * 64 + t * 2 + 1];
        float v0 = __half2float(sV[rr * SDH + j]);
        float v1 = __half2float(sV[(rr + 16) * SDH + j]);
        ctxH[t * SDH + j] = __float2half(w0 * v0 + w1 * v1);
    }
}

// ---------------- layernorm over 32 tokens (fp32 master, opt fp16 shadow) ----
__device__ __forceinline__ void layernorm32(float* buf, const float* __restrict__ g,
                                            const float* __restrict__ b,
                                            __half* shadow) {
    const int tid = threadIdx.x;
    const int wid = tid >> 5, lane = tid & 31;
    for (int t = wid; t < 32; t += 8) {
        float s = 0.f, sq = 0.f;
        float vv[6];
#pragma unroll
        for (int e = 0; e < 6; e++) {
            float x = buf[t * SD + lane + e * 32];
            vv[e] = x; s += x; sq += x * x;
        }
#pragma unroll
        for (int o = 16; o; o >>= 1) {
            s += __shfl_xor_sync(0xffffffffu, s, o);
            sq += __shfl_xor_sync(0xffffffffu, sq, o);
        }
        float mu = s * (1.f / Dm);
        float var = sq * (1.f / Dm) - mu * mu;
        float rstd = rsqrtf(var + 1e-5f);
#pragma unroll
        for (int e = 0; e < 6; e++) {
            int j = lane + e * 32;
            float y = (vv[e] - mu) * rstd * g[j] + b[j];
            buf[t * SD + j] = y;
            if (shadow) shadow[t * SDH + j] = __float2half(y);
        }
    }
}

__global__ __launch_bounds__(NTH, 2)
void fusion_kernel(const float* __restrict__ perc, const float* __restrict__ tech,
                   const float* __restrict__ bp,  const float* __restrict__ bt,
                   const float* __restrict__ out_b,
                   const float* __restrict__ f1b, const float* __restrict__ f2b,
                   const float* __restrict__ ln1g, const float* __restrict__ ln1b,
                   const float* __restrict__ ln2g, const float* __restrict__ ln2b,
                   const float* __restrict__ c1b, const float* __restrict__ c2w,
                   const float* __restrict__ c2b, const float* __restrict__ fpb,
                   float* __restrict__ out, int B)
{
    extern __shared__ float smem[];
    float*  sB   = smem + OFB;
    __half* sP0  = (__half*)(smem + OFP0);   // q -> ctx ; hidden lo ; cls out
    __half* sP1  = (__half*)(smem + OFP1);   // k ; hidden hi
    __half* sP2  = (__half*)(smem + OFP2);   // input/v ; x-shadow -> z
    float*  sClsF = smem + OFP0;             // fp32 view for cls1 out
    __half* sWH  = (__half*)(smem + OFW);
    float*  sMisc = smem + OFMISC;

    const int tid = threadIdx.x;
    const int r0b = blockIdx.x * ROWSn;

    // 1. stage inputs fp16, GROUPED: rows 0..15 perc, 16..31 tech -> P2
    for (int idx = tid; idx < 32 * 48; idx += NTH) {
        int t = idx / 48;
        int c4 = (idx % 48) * 4;
        const float* src = (t < 16) ? perc : tech;
        int row = (t < 16) ? t : t - 16;
        float4 v = *(const float4*)&src[(size_t)(r0b + row) * Dm + c4];
        *(__half2*)&sP2[t * SDH + c4] = __floats2half2_rn(v.x, v.y);
        *(__half2*)&sP2[t * SDH + c4 + 2] = __floats2half2_rn(v.z, v.w);
    }

    // 2. proj (dual Wp/Wt) -> sB fp32 (seq)
    gemm192(sP2, SDH, g_hWp, g_hWt, 192, 0, 3,
            bp, bt, sB, SD, nullptr, 0, 0, false, false, false, sWH);
    __syncthreads();
    for (int idx = tid; idx < 32 * 192; idx += NTH) {
        int t = idx / 192, j = idx % 192;
        sB[t * SD + j] += out_b[j];     // pre-add out-proj bias to residual
    }

    // 3. qkv via fused weights: q->P0, k->P1, v->P2 (in-place over input)
    gemm192(sP2, SDH, g_hQp, g_hQt, 576, 0, 3,
            g_bQp, g_bQt, nullptr, 0, sP0, SDH, 0, false, false, false, sWH);
    gemm192(sP2, SDH, g_hQp, g_hQt, 576, 192, 3,
            g_bQp, g_bQt, nullptr, 0, sP1, SDH, 0, false, false, false, sWH);
    gemm192(sP2, SDH, g_hQp, g_hQt, 576, 384, 3,
            g_bQp, g_bQt, nullptr, 0, sP2, SDH, 0, false, false, true, sWH);
    __syncthreads();   // v writes visible before attention reads

    // 4. attention; ctx overwrites q (P0)
    attention_all(sP0, sP1, sP2, sP0, sMisc);

    // 5. out-proj: sB += ctx @ out_w^T
    gemm192(sP0, SDH, g_hOut, nullptr, 192, 0, 3,
            nullptr, nullptr, sB, SD, nullptr, 0, 0, true, false, false, sWH);
    __syncthreads();
    layernorm32(sB, ln1g, ln1b, sP2);   // x in sB + fp16 shadow in P2

    // 6. FFN1 -> hidden fp16 [32][SHD] over P0+P1
    __half* sHH = sP0;
    gemm192(sP2, SDH, g_hF1, nullptr, 384, 0, 3,
            f1b, nullptr, nullptr, 0, sHH, SHD, 0, false, true, false, sWH);
    gemm192(sP2, SDH, g_hF1, nullptr, 384, 192, 3,
            f1b, nullptr, nullptr, 0, sHH, SHD, 192, false, true, false, sWH);

    // 7. FFN2 (K=384, nk=6) accumulate onto x; LN2
    gemm192(sHH, SHD, g_hF2, nullptr, 192, 0, 6,
            f2b, nullptr, sB, SD, nullptr, 0, 0, true, false, false, sWH);
    __syncthreads();
    layernorm32(sB, ln2g, ln2b, nullptr);
    __syncthreads();

    // 8. z = mean of pair (r, r+16) -> fp16 P2 rows 0..15 (16..31 stale, finite)
    for (int idx = tid; idx < 16 * 192; idx += NTH) {
        int r = idx / 192, j = idx % 192;
        sP2[r * SDH + j] =
            __float2half(0.5f * (sB[r * SD + j] + sB[(r + 16) * SD + j]));
    }

    // 9. cls1 = relu(z@W^T + b) -> fp32 over P0+P1 (rows 16..31 garbage)
    gemm192(sP2, SDH, g_hC1, nullptr, 192, 0, 3,
            c1b, nullptr, sClsF, SD, nullptr, 0, 0, false, true, false, sWH);
    __syncthreads();

    // 10. logits + sigmoid
    if (tid < 48) {
        int r = tid / 3, c = tid % 3;
        float s = c2b[c];
        const float* w = c2w + c * Dm;
        const float* x = sClsF + r * SD;
#pragma unroll 8
        for (int kk = 0; kk < Dm; ++kk) s += x[kk] * w[kk];
        out[(size_t)c * B + r0b + r] = 1.f / (1.f + __expf(-s));
    }

    // 11. fp = z @ fp_w^T -> sB (x dead); bias at normalize
    gemm192(sP2, SDH, g_hFp2, nullptr, 192, 0, 3,
            nullptr, nullptr, sB, SD, nullptr, 0, 0, false, false, false, sWH);
    __syncthreads();
    {
        const int wid = tid >> 5, lane = tid & 31;
        for (int r = wid; r < ROWSn; r += 8) {
            float ss = 0.f;
            float v[4];
#pragma unroll
            for (int e = 0; e < 4; ++e) {
                int col = lane + e * 32;
                v[e] = sB[r * SD + col] + fpb[col];
                ss += v[e] * v[e];
            }
#pragma unroll
            for (int o = 16; o; o >>= 1) ss += __shfl_xor_sync(0xffffffffu, ss, o);
            float inv = 1.f / fmaxf(sqrtf(ss), 1e-12f);
#pragma unroll
            for (int e = 0; e < 4; ++e)
                out[(size_t)3 * B + (size_t)(r0b + r) * 128 + lane + e * 32] = v[e] * inv;
        }
    }
}

// ---------------- host ----------------
extern "C" void kernel_launch(void* const* d_in, const int* in_sizes, int n_in,
                              void* d_out, int out_size) {
    const float* perc = (const float*)d_in[0];
    const float* tech = (const float*)d_in[1];
    const float* Wp   = (const float*)d_in[2];
    const float* bp   = (const float*)d_in[3];
    const float* Wt   = (const float*)d_in[4];
    const float* bt   = (const float*)d_in[5];
    const float* in_w = (const float*)d_in[6];
    const float* in_b = (const float*)d_in[7];
    const float* out_w= (const float*)d_in[8];
    const float* out_b= (const float*)d_in[9];
    const float* f1w  = (const float*)d_in[10];
    const float* f1b  = (const float*)d_in[11];
    const float* f2w  = (const float*)d_in[12];
    const float* f2b  = (const float*)d_in[13];
    const float* ln1g = (const float*)d_in[14];
    const float* ln1b = (const float*)d_in[15];
    const float* ln2g = (const float*)d_in[16];
    const float* ln2b = (const float*)d_in[17];
    const float* c1w  = (const float*)d_in[18];
    const float* c1b  = (const float*)d_in[19];
    const float* c2w  = (const float*)d_in[20];
    const float* c2b  = (const float*)d_in[21];
    const float* fpw  = (const float*)d_in[22];
    const float* fpb  = (const float*)d_in[23];
    float* out = (float*)d_out;
    const int B = in_sizes[0] / Dm;

    prep_kernel<<<512, 256>>>(Wp, Wt, in_w, in_b, bp, bt,
                              out_w, f1w, f2w, c1w, fpw);

    cudaFuncSetAttribute(fusion_kernel,
                         cudaFuncAttributeMaxDynamicSharedMemorySize, SMEM_BYTES);
    fusion_kernel<<<B / ROWSn, NTH, SMEM_BYTES>>>(
        perc, tech, bp, bt, out_b, f1b, f2b,
        ln1g, ln1b, ln2g, ln2b, c1b, c2w, c2b, fpb, out, B);
}

// round 13
// speedup vs baseline: 1.4564x; 1.4564x over previous
#include <cuda_runtime.h>
#include <cuda_fp16.h>
#include <cstdint>
#include <math.h>

#define NTH 512
#define NB  65536

// ---------------- device scratch (static, no allocs) ----------------
__device__ __half g_Xh [2u * NB * 192];   // grouped inputs fp16
__device__ float  g_seq[2u * NB * 192];   // proj residual base (+out_b)
__device__ __half g_qkv[2u * NB * 576];
__device__ __half g_ctx[2u * NB * 192];
__device__ float  g_xf [2u * NB * 192];   // x after LN1 (fp32)
__device__ __half g_xh [2u * NB * 192];   // x after LN1 (fp16)
__device__ __half g_hh [2u * NB * 384];   // FFN hidden
__device__ float  g_y2 [2u * NB * 192];   // pre-LN2 sum
__device__ __half g_zh [(size_t)NB * 192];// pooled z fp16

// ---------------- fp16 k-major weights ----------------
__device__ __align__(16) __half g_hWp[192 * 192];
__device__ __align__(16) __half g_hWt[192 * 192];
__device__ __align__(16) __half g_hQp[192 * 576];
__device__ __align__(16) __half g_hQt[192 * 576];
__device__ __align__(16) __half g_hOut[192 * 192];
__device__ __align__(16) __half g_hF1[192 * 384];
__device__ __align__(16) __half g_hF2[384 * 192];
__device__ __align__(16) __half g_hC1[192 * 192];
__device__ __align__(16) __half g_hFp2[192 * 192];
__device__ float g_bQp[576], g_bQt[576];
__device__ float g_bSeqP[192], g_bSeqT[192];

__device__ __forceinline__ void cp_async16(uint32_t dst, const void* src) {
    asm volatile("cp.async.cg.shared.global [%0], [%1], 16;\n" :: "r"(dst), "l"(src));
}

__global__ void prep_kernel(const float* Wp, const float* Wt, const float* in_w,
                            const float* in_b, const float* bp, const float* bt,
                            const float* out_w, const float* f1w, const float* f2w,
                            const float* c1w, const float* fpw, const float* out_b) {
    const int t0 = blockIdx.x * blockDim.x + threadIdx.x;
    const int nthr = gridDim.x * blockDim.x;
    {
        const float* srcs[6] = {Wp, Wt, out_w, f1w, f2w, c1w};
        __half* dsts[6] = {g_hWp, g_hWt, g_hOut, g_hF1, g_hF2, g_hC1};
        const int Rs[6] = {192, 192, 192, 384, 192, 192};
        const int Cs[6] = {192, 192, 192, 192, 384, 192};
#pragma unroll 1
        for (int m = 0; m < 6; ++m) {
            int n = Rs[m] * Cs[m];
            for (int d = t0; d < n; d += nthr) {
                int k = d / Rs[m], j = d % Rs[m];
                dsts[m][d] = __float2half(srcs[m][j * Cs[m] + k]);
            }
        }
    }
    for (int d = t0; d < 192 * 192; d += nthr) {
        int k = d / 192, j = d % 192;
        g_hFp2[d] = __float2half(j < 128 ? fpw[j * 192 + k] : 0.f);
    }
    for (int d = t0; d < 192 * 576; d += nthr) {
        int k = d / 576, j = d % 576;
        float sp = 0.f, st = 0.f;
        const float* iw = in_w + (size_t)j * 192;
#pragma unroll 4
        for (int m = 0; m < 192; ++m) {
            float w = iw[m];
            sp += w * Wp[m * 192 + k];
            st += w * Wt[m * 192 + k];
        }
        g_hQp[d] = __float2half(sp);
        g_hQt[d] = __float2half(st);
    }
    for (int j = t0; j < 576; j += nthr) {
        float sp = in_b[j], st = in_b[j];
        const float* iw = in_w + (size_t)j * 192;
#pragma unroll 4
        for (int m = 0; m < 192; ++m) {
            float w = iw[m];
            sp += w * bp[m];
            st += w * bt[m];
        }
        g_bQp[j] = sp;
        g_bQt[j] = st;
    }
    for (int j = t0; j < 192; j += nthr) {
        g_bSeqP[j] = bp[j] + out_b[j];
        g_bSeqT[j] = bt[j] + out_b[j];
    }
}

#define MMA16(dd, a0, a1, a2, a3, b0, b1)                                        \
    asm volatile("mma.sync.aligned.m16n8k16.row.col.f32.f16.f16.f32 "            \
                 "{%0,%1,%2,%3}, {%4,%5,%6,%7}, {%8,%9}, {%0,%1,%2,%3};"         \
                 : "+f"(dd[0]), "+f"(dd[1]), "+f"(dd[2]), "+f"(dd[3])            \
                 : "r"(a0), "r"(a1), "r"(a2), "r"(a3), "r"(b0), "r"(b1))

// ---------------- streaming GEMM mainloop ----------------
// Per CTA: W slice [K][192] loaded ONCE (smem stride 200). A streamed in
// [MT][64] chunks (smem stride 72), 4-slot ring, prefetch 2 ahead, ONE barrier
// per chunk. 16 warps: mw=wid&3 (MT/4 rows), nw=wid>>2 (48 cols).
// epi(mt, d) called when a tile's K accumulation completes.
template<int MT, class Epi>
__device__ __forceinline__ void run_gemm(
    const __half* __restrict__ A, int lda, int rowbase,
    const __half* __restrict__ W, int ldw, int jw0, int K,
    int mtiles, Epi epi)
{
    extern __shared__ float smemf[];
    __half* sA = (__half*)smemf;
    __half* sW = sA + 4 * MT * 72;
    constexpr int RM = MT / 64;
    const int tid = threadIdx.x;
    const int wid = tid >> 5, lane = tid & 31;
    const int mw = wid & 3, nw = wid >> 2;
    const int r0 = mw * (MT / 4);
    const int nk = K >> 6;
    const int bx = blockIdx.x, gxs = gridDim.x;

    const uint32_t sAu = (uint32_t)__cvta_generic_to_shared(sA);
    const uint32_t sWu = (uint32_t)__cvta_generic_to_shared(sW);

    // load full W slice
    {
        int nseg = K * 24;
        for (int s = tid; s < nseg; s += NTH) {
            int row = s / 24, col = (s % 24) << 3;
            cp_async16(sWu + (uint32_t)((row * 200 + col) * 2),
                       W + (size_t)row * ldw + jw0 + col);
        }
        asm volatile("cp.async.commit_group;\n" ::: "memory");
    }

    const int nIter = (mtiles > bx) ? ((mtiles - bx + gxs - 1) / gxs) : 0;
    const int Q = nIter * nk;

    auto issueA = [&](int q) {
        int it = q / nk, kc = q - it * nk;
        int mt = bx + it * gxs;
        const __half* src = A + (size_t)(rowbase + mt * MT) * lda + kc * 64;
        uint32_t dst = sAu + (uint32_t)((q & 3) * MT * 72 * 2);
#pragma unroll
        for (int i = 0; i < (MT * 8) / NTH; ++i) {
            int s = tid + i * NTH;
            int row = s >> 3, cs = (s & 7) << 3;
            cp_async16(dst + (uint32_t)((row * 72 + cs) * 2),
                       src + (size_t)row * lda + cs);
        }
        asm volatile("cp.async.commit_group;\n" ::: "memory");
    };
    if (Q > 0) issueA(0);
    if (Q > 1) issueA(1);

    float d[RM][6][4];
#pragma unroll
    for (int rm = 0; rm < RM; ++rm)
#pragma unroll
        for (int nt = 0; nt < 6; ++nt)
            d[rm][nt][0] = d[rm][nt][1] = d[rm][nt][2] = d[rm][nt][3] = 0.f;

    const int bk = (lane & 7) | (lane & 8);
    const int bn = nw * 48 + ((lane >> 4) << 3);
    const uint32_t aoff = (uint32_t)(((r0 + (lane & 15)) * 72 + ((lane >> 4) << 3)) * 2);

    int kc = 0, mtc = bx;
    for (int q = 0; q < Q; ++q) {
        if (q + 2 < Q) {
            issueA(q + 2);
            asm volatile("cp.async.wait_group 2;\n" ::: "memory");
        } else if (q + 1 < Q) {
            asm volatile("cp.async.wait_group 1;\n" ::: "memory");
        } else {
            asm volatile("cp.async.wait_group 0;\n" ::: "memory");
        }
        __syncthreads();
        uint32_t aAddr0 = sAu + (uint32_t)((q & 3) * MT * 72 * 2) + aoff;
#pragma unroll
        for (int ks = 0; ks < 4; ++ks) {
            uint32_t af[RM][4];
#pragma unroll
            for (int rm = 0; rm < RM; ++rm)
                asm volatile("ldmatrix.sync.aligned.m8n8.x4.shared.b16 {%0,%1,%2,%3}, [%4];"
                             : "=r"(af[rm][0]), "=r"(af[rm][1]),
                               "=r"(af[rm][2]), "=r"(af[rm][3])
                             : "r"(aAddr0 + (uint32_t)((rm * 16 * 72 + ks * 16) * 2)));
            uint32_t bRow = sWu + (uint32_t)(((kc * 64 + ks * 16 + bk) * 200 + bn) * 2);
#pragma unroll
            for (int gi = 0; gi < 3; ++gi) {
                uint32_t b0, b1, b2, b3;
                asm volatile("ldmatrix.sync.aligned.m8n8.x4.trans.shared.b16 "
                             "{%0,%1,%2,%3}, [%4];"
                             : "=r"(b0), "=r"(b1), "=r"(b2), "=r"(b3)
                             : "r"(bRow + (uint32_t)(gi * 16 * 2)));
#pragma unroll
                for (int rm = 0; rm < RM; ++rm) {
                    MMA16(d[rm][gi * 2],     af[rm][0], af[rm][1], af[rm][2], af[rm][3], b0, b1);
                    MMA16(d[rm][gi * 2 + 1], af[rm][0], af[rm][1], af[rm][2], af[rm][3], b2, b3);
                }
            }
        }
        if (++kc == nk) {
            kc = 0;
            epi(mtc, d);
            mtc += gxs;
#pragma unroll
            for (int rm = 0; rm < RM; ++rm)
#pragma unroll
                for (int nt = 0; nt < 6; ++nt)
                    d[rm][nt][0] = d[rm][nt][1] = d[rm][nt][2] = d[rm][nt][3] = 0.f;
        }
    }
}

// ---------------- generic M128 GEMM (plain epilogue) ----------------
// grid: (gx, ntiles, groups). group z selects W/bias and row base z*B.
__global__ __launch_bounds__(NTH, 1)
void k_gemm128(const __half* __restrict__ A, int lda,
               const __half* __restrict__ W0, const __half* __restrict__ W1,
               int ldw, const float* __restrict__ bias0,
               const float* __restrict__ bias1,
               int K, int mtiles, int B,
               __half* __restrict__ outH, float* __restrict__ outF,
               const float* __restrict__ resid, int ldo, int relu)
{
    const int zz = blockIdx.z;
    const __half* W = zz ? W1 : W0;
    const float* bias = zz ? bias1 : bias0;
    const int jw0 = blockIdx.y * 192;
    const int rowbase = zz * B;
    const int tid = threadIdx.x;
    const int wid = tid >> 5, lane = tid & 31;
    const int mw = wid & 3, nw = wid >> 2;
    const int g = lane >> 2, c = lane & 3;
    const int r0 = mw * 32;

    run_gemm<128>(A, lda, rowbase, W, ldw, jw0, K, mtiles,
        [&](int mt, auto& d) {
#pragma unroll
            for (int rm = 0; rm < 2; ++rm) {
                size_t rA = (size_t)rowbase + (size_t)mt * 128 + r0 + rm * 16 + g;
                size_t rB = rA + 8;
#pragma unroll
                for (int nt = 0; nt < 6; ++nt) {
                    int jc = nw * 48 + nt * 8 + 2 * c;
                    float bx = bias[jw0 + jc], by = bias[jw0 + jc + 1];
                    float2 v0 = make_float2(d[rm][nt][0] + bx, d[rm][nt][1] + by);
                    float2 v1 = make_float2(d[rm][nt][2] + bx, d[rm][nt][3] + by);
                    if (relu) {
                        v0.x = fmaxf(v0.x, 0.f); v0.y = fmaxf(v0.y, 0.f);
                        v1.x = fmaxf(v1.x, 0.f); v1.y = fmaxf(v1.y, 0.f);
                    }
                    if (resid) {
                        float2 s0 = *(const float2*)&resid[rA * 192 + jc];
                        float2 s1 = *(const float2*)&resid[rB * 192 + jc];
                        v0.x += s0.x; v0.y += s0.y; v1.x += s1.x; v1.y += s1.y;
                    }
                    if (outF) {
                        *(float2*)&outF[rA * ldo + jw0 + jc] = v0;
                        *(float2*)&outF[rB * ldo + jw0 + jc] = v1;
                    }
                    if (outH) {
                        *(__half2*)&outH[rA * ldo + jw0 + jc] = __floats2half2_rn(v0.x, v0.y);
                        *(__half2*)&outH[rB * ldo + jw0 + jc] = __floats2half2_rn(v1.x, v1.y);
                    }
                }
            }
        });
}

#define STAGEF (smemf + 28416)   // (4*64*72 + 192*200) halves = 113664 B

// ---------------- out-proj + residual + LN1 (M64, fused) ----------------
__global__ __launch_bounds__(NTH, 1)
void k_ln1(const __half* __restrict__ ctx, const __half* __restrict__ Wout,
           const float* __restrict__ seq, const float* __restrict__ lng,
           const float* __restrict__ lnb, float* __restrict__ xf,
           __half* __restrict__ xh, int mtiles)
{
    extern __shared__ float smemf[];
    float* stage = STAGEF;
    const int tid = threadIdx.x;
    const int wid = tid >> 5, lane = tid & 31;
    const int mw = wid & 3, nw = wid >> 2;
    const int g = lane >> 2, c = lane & 3;
    const int r0 = mw * 16;

    run_gemm<64>(ctx, 192, 0, Wout, 192, 0, 192, mtiles,
        [&](int mt, auto& d) {
            int rA = r0 + g, rB = rA + 8;
            size_t gA = (size_t)mt * 64 + rA, gB = gA + 8;
#pragma unroll
            for (int nt = 0; nt < 6; ++nt) {
                int jc = nw * 48 + nt * 8 + 2 * c;
                float2 s0 = *(const float2*)&seq[gA * 192 + jc];
                float2 s1 = *(const float2*)&seq[gB * 192 + jc];
                stage[rA * 196 + jc]     = d[0][nt][0] + s0.x;
                stage[rA * 196 + jc + 1] = d[0][nt][1] + s0.y;
                stage[rB * 196 + jc]     = d[0][nt][2] + s1.x;
                stage[rB * 196 + jc + 1] = d[0][nt][3] + s1.y;
            }
            __syncthreads();
#pragma unroll
            for (int t = 0; t < 4; ++t) {
                int row = wid * 4 + t;
                float vv[6], s = 0.f, sq = 0.f;
#pragma unroll
                for (int e = 0; e < 6; ++e) {
                    float x = stage[row * 196 + lane + e * 32];
                    vv[e] = x; s += x; sq += x * x;
                }
#pragma unroll
                for (int o = 16; o; o >>= 1) {
                    s += __shfl_xor_sync(0xffffffffu, s, o);
                    sq += __shfl_xor_sync(0xffffffffu, sq, o);
                }
                float mu = s * (1.f / 192.f);
                float var = sq * (1.f / 192.f) - mu * mu;
                float rstd = rsqrtf(var + 1e-5f);
                size_t grow = (size_t)mt * 64 + row;
#pragma unroll
                for (int e = 0; e < 6; ++e) {
                    int j = lane + e * 32;
                    float y = (vv[e] - mu) * rstd * lng[j] + lnb[j];
                    xf[grow * 192 + j] = y;
                    xh[grow * 192 + j] = __float2half(y);
                }
            }
            __syncthreads();
        });
}

// ---------------- cls head: z@C1 relu, then logits+sigmoid (M64) ----------------
__global__ __launch_bounds__(NTH, 1)
void k_cls(const __half* __restrict__ zh, const __half* __restrict__ Wc1,
           const float* __restrict__ c1b, const float* __restrict__ c2w,
           const float* __restrict__ c2b, float* __restrict__ outp,
           int B, int mtiles)
{
    extern __shared__ float smemf[];
    float* stage = STAGEF;
    const int tid = threadIdx.x;
    const int wid = tid >> 5, lane = tid & 31;
    const int mw = wid & 3, nw = wid >> 2;
    const int g = lane >> 2, c = lane & 3;
    const int r0 = mw * 16;

    run_gemm<64>(zh, 192, 0, Wc1, 192, 0, 192, mtiles,
        [&](int mt, auto& d) {
            int rA = r0 + g, rB = rA + 8;
#pragma unroll
            for (int nt = 0; nt < 6; ++nt) {
                int jc = nw * 48 + nt * 8 + 2 * c;
                float bx = c1b[jc], by = c1b[jc + 1];
                stage[rA * 196 + jc]     = fmaxf(d[0][nt][0] + bx, 0.f);
                stage[rA * 196 + jc + 1] = fmaxf(d[0][nt][1] + by, 0.f);
                stage[rB * 196 + jc]     = fmaxf(d[0][nt][2] + bx, 0.f);
                stage[rB * 196 + jc + 1] = fmaxf(d[0][nt][3] + by, 0.f);
            }
            __syncthreads();
            if (tid < 192) {
                int row = tid / 3, cls = tid - row * 3;
                float s = c2b[cls];
                const float* w = c2w + cls * 192;
                const float* x = stage + row * 196;
#pragma unroll 8
                for (int kk = 0; kk < 192; ++kk) s += x[kk] * w[kk];
                outp[(size_t)cls * B + (size_t)mt * 64 + row] =
                    1.f / (1.f + __expf(-s));
            }
            __syncthreads();
        });
}

// ---------------- fp head: z@Fp + b, row-normalize (M64) ----------------
__global__ __launch_bounds__(NTH, 1)
void k_fp(const __half* __restrict__ zh, const __half* __restrict__ Wfp,
          const float* __restrict__ fpb, float* __restrict__ outp,
          int B, int mtiles)
{
    extern __shared__ float smemf[];
    float* stage = STAGEF;
    const int tid = threadIdx.x;
    const int wid = tid >> 5, lane = tid & 31;
    const int mw = wid & 3, nw = wid >> 2;
    const int g = lane >> 2, c = lane & 3;
    const int r0 = mw * 16;

    run_gemm<64>(zh, 192, 0, Wfp, 192, 0, 192, mtiles,
        [&](int mt, auto& d) {
            int rA = r0 + g, rB = rA + 8;
#pragma unroll
            for (int nt = 0; nt < 6; ++nt) {
                int jc = nw * 48 + nt * 8 + 2 * c;
                float bx = (jc < 128) ? fpb[jc] : 0.f;
                float by = (jc + 1 < 128) ? fpb[jc + 1] : 0.f;
                stage[rA * 196 + jc]     = d[0][nt][0] + bx;
                stage[rA * 196 + jc + 1] = d[0][nt][1] + by;
                stage[rB * 196 + jc]     = d[0][nt][2] + bx;
                stage[rB * 196 + jc + 1] = d[0][nt][3] + by;
            }
            __syncthreads();
#pragma unroll
            for (int t = 0; t < 4; ++t) {
                int row = wid * 4 + t;
                float v[4], ss = 0.f;
#pragma unroll
                for (int e = 0; e < 4; ++e) {
                    v[e] = stage[row * 196 + lane + e * 32];
                    ss += v[e] * v[e];
                }
#pragma unroll
                for (int o = 16; o; o >>= 1) ss += __shfl_xor_sync(0xffffffffu, ss, o);
                float inv = 1.f / fmaxf(sqrtf(ss), 1e-12f);
                size_t grow = (size_t)mt * 64 + row;
#pragma unroll
                for (int e = 0; e < 4; ++e)
                    outp[(size_t)3 * B + grow * 128 + lane + e * 32] = v[e] * inv;
            }
            __syncthreads();
        });
}

// ---------------- small kernels ----------------
__global__ void k_convert(const float* __restrict__ perc,
                          const float* __restrict__ tech,
                          __half* __restrict__ Xh, int B) {
    int n4 = B * 48;
    for (int idx = blockIdx.x * blockDim.x + threadIdx.x; idx < n4;
         idx += gridDim.x * blockDim.x) {
        int e = idx / 48, c4 = (idx % 48) * 4;
        float4 vp = *(const float4*)&perc[(size_t)e * 192 + c4];
        float4 vt = *(const float4*)&tech[(size_t)e * 192 + c4];
        *(__half2*)&g_Xh[(size_t)e * 192 + c4]     = __floats2half2_rn(vp.x, vp.y);
        *(__half2*)&g_Xh[(size_t)e * 192 + c4 + 2] = __floats2half2_rn(vp.z, vp.w);
        *(__half2*)&Xh[((size_t)B + e) * 192 + c4]     = __floats2half2_rn(vt.x, vt.y);
        *(__half2*)&Xh[((size_t)B + e) * 192 + c4 + 2] = __floats2half2_rn(vt.z, vt.w);
    }
}

__global__ void k_attn(const __half* __restrict__ qkv, __half* __restrict__ ctx,
                       int B) {
    int gw = (blockIdx.x * blockDim.x + threadIdx.x) >> 5;
    int lane = threadIdx.x & 31;
    int nwarps = (gridDim.x * blockDim.x) >> 5;
    for (int e = gw; e < B; e += nwarps) {
        const __half2* r0 = (const __half2*)(qkv + (size_t)e * 576);
        const __half2* r1 = (const __half2*)(qkv + ((size_t)B + e) * 576);
        __half2* c0 = (__half2*)(ctx + (size_t)e * 192);
        __half2* c1 = (__half2*)(ctx + ((size_t)B + e) * 192);
#pragma unroll
        for (int h = 0; h < 3; ++h) {
            int o = h * 32 + lane;
            float2 q0 = __half22float2(r0[o]),      q1 = __half22float2(r1[o]);
            float2 k0 = __half22float2(r0[96 + o]), k1 = __half22float2(r1[96 + o]);
            float d00 = q0.x * k0.x + q0.y * k0.y;
            float d01 = q0.x * k1.x + q0.y * k1.y;
            float d10 = q1.x * k0.x + q1.y * k0.y;
            float d11 = q1.x * k1.x + q1.y * k1.y;
#pragma unroll
            for (int s = 16; s; s >>= 1) {
                d00 += __shfl_xor_sync(0xffffffffu, d00, s);
                d01 += __shfl_xor_sync(0xffffffffu, d01, s);
                d10 += __shfl_xor_sync(0xffffffffu, d10, s);
                d11 += __shfl_xor_sync(0xffffffffu, d11, s);
            }
            const float sc = 0.125f;
            d00 *= sc; d01 *= sc; d10 *= sc; d11 *= sc;
            float m0 = fmaxf(d00, d01), m1 = fmaxf(d10, d11);
            float e00 = __expf(d00 - m0), e01 = __expf(d01 - m0);
            float e10 = __expf(d10 - m1), e11 = __expf(d11 - m1);
            float i0 = 1.f / (e00 + e01), i1 = 1.f / (e10 + e11);
            float a00 = e00 * i0, a01 = e01 * i0;
            float a10 = e10 * i1, a11 = e11 * i1;
            float2 v0 = __half22float2(r0[192 + o]);
            float2 v1 = __half22float2(r1[192 + o]);
            c0[o] = __floats2half2_rn(a00 * v0.x + a01 * v1.x,
                                      a00 * v0.y + a01 * v1.y);
            c1[o] = __floats2half2_rn(a10 * v0.x + a11 * v1.x,
                                      a10 * v0.y + a11 * v1.y);
        }
    }
}

__global__ void k_lnz(const float* __restrict__ y2, const float* __restrict__ lng,
                      const float* __restrict__ lnb, __half* __restrict__ zh,
                      int B) {
    int gw = (blockIdx.x * blockDim.x + threadIdx.x) >> 5;
    int lane = threadIdx.x & 31;
    int nwarps = (gridDim.x * blockDim.x) >> 5;
    for (int e = gw; e < B; e += nwarps) {
        float a[6], b6[6];
        float sa = 0.f, qa = 0.f, sb = 0.f, qb = 0.f;
#pragma unroll
        for (int k = 0; k < 6; ++k) {
            int j = lane + k * 32;
            a[k] = y2[(size_t)e * 192 + j];
            b6[k] = y2[((size_t)B + e) * 192 + j];
            sa += a[k]; qa += a[k] * a[k];
            sb += b6[k]; qb += b6[k] * b6[k];
        }
#pragma unroll
        for (int s = 16; s; s >>= 1) {
            sa += __shfl_xor_sync(0xffffffffu, sa, s);
            qa += __shfl_xor_sync(0xffffffffu, qa, s);
            sb += __shfl_xor_sync(0xffffffffu, sb, s);
            qb += __shfl_xor_sync(0xffffffffu, qb, s);
        }
        float mua = sa / 192.f, mub = sb / 192.f;
        float ra = rsqrtf(qa / 192.f - mua * mua + 1e-5f);
        float rb = rsqrtf(qb / 192.f - mub * mub + 1e-5f);
#pragma unroll
        for (int k = 0; k < 6; ++k) {
            int j = lane + k * 32;
            float ya = (a[k] - mua) * ra * lng[j] + lnb[j];
            float yb = (b6[k] - mub) * rb * lng[j] + lnb[j];
            zh[(size_t)e * 192 + j] = __float2half(0.5f * (ya + yb));
        }
    }
}

// ---------------- host ----------------
#define SM_G192 150528
#define SM_G384 227328
#define SM_LN   163840

extern "C" void kernel_launch(void* const* d_in, const int* in_sizes, int n_in,
                              void* d_out, int out_size) {
    const float* perc = (const float*)d_in[0];
    const float* tech = (const float*)d_in[1];
    const float* Wp   = (const float*)d_in[2];
    const float* bp   = (const float*)d_in[3];
    const float* Wt   = (const float*)d_in[4];
    const float* bt   = (const float*)d_in[5];
    const float* in_w = (const float*)d_in[6];
    const float* in_b = (const float*)d_in[7];
    const float* out_w= (const float*)d_in[8];
    const float* out_b= (const float*)d_in[9];
    const float* f1w  = (const float*)d_in[10];
    const float* f1b  = (const float*)d_in[11];
    const float* f2w  = (const float*)d_in[12];
    const float* f2b  = (const float*)d_in[13];
    const float* ln1g = (const float*)d_in[14];
    const float* ln1b = (const float*)d_in[15];
    const float* ln2g = (const float*)d_in[16];
    const float* ln2b = (const float*)d_in[17];
    const float* c1w  = (const float*)d_in[18];
    const float* c1b  = (const float*)d_in[19];
    const float* c2w  = (const float*)d_in[20];
    const float* c2b  = (const float*)d_in[21];
    const float* fpw  = (const float*)d_in[22];
    const float* fpb  = (const float*)d_in[23];
    float* out = (float*)d_out;
    const int B = in_sizes[0] / 192;

    static int inited = 0;
    if (!inited) {
        inited = 1;
        cudaFuncSetAttribute(k_gemm128, cudaFuncAttributeMaxDynamicSharedMemorySize, SM_G384);
        cudaFuncSetAttribute(k_ln1, cudaFuncAttributeMaxDynamicSharedMemorySize, SM_LN);
        cudaFuncSetAttribute(k_cls, cudaFuncAttributeMaxDynamicSharedMemorySize, SM_LN);
        cudaFuncSetAttribute(k_fp,  cudaFuncAttributeMaxDynamicSharedMemorySize, SM_LN);
    }

    __half *Xh, *qkv, *ctx, *xh, *hh, *zh;
    float *seq, *xf, *y2;
    cudaGetSymbolAddress((void**)&Xh,  g_Xh);
    cudaGetSymbolAddress((void**)&qkv, g_qkv);
    cudaGetSymbolAddress((void**)&ctx, g_ctx);
    cudaGetSymbolAddress((void**)&xh,  g_xh);
    cudaGetSymbolAddress((void**)&hh,  g_hh);
    cudaGetSymbolAddress((void**)&zh,  g_zh);
    cudaGetSymbolAddress((void**)&seq, g_seq);
    cudaGetSymbolAddress((void**)&xf,  g_xf);
    cudaGetSymbolAddress((void**)&y2,  g_y2);

    __half *hWp, *hWt, *hQp, *hQt, *hOut, *hF1, *hF2, *hC1, *hFp2;
    float *bQp, *bQt, *bSP, *bST;
    cudaGetSymbolAddress((void**)&hWp, g_hWp);
    cudaGetSymbolAddress((void**)&hWt, g_hWt);
    cudaGetSymbolAddress((void**)&hQp, g_hQp);
    cudaGetSymbolAddress((void**)&hQt, g_hQt);
    cudaGetSymbolAddress((void**)&hOut, g_hOut);
    cudaGetSymbolAddress((void**)&hF1, g_hF1);
    cudaGetSymbolAddress((void**)&hF2, g_hF2);
    cudaGetSymbolAddress((void**)&hC1, g_hC1);
    cudaGetSymbolAddress((void**)&hFp2, g_hFp2);
    cudaGetSymbolAddress((void**)&bQp, g_bQp);
    cudaGetSymbolAddress((void**)&bQt, g_bQt);
    cudaGetSymbolAddress((void**)&bSP, g_bSeqP);
    cudaGetSymbolAddress((void**)&bST, g_bSeqT);

    prep_kernel<<<512, 256>>>(Wp, Wt, in_w, in_b, bp, bt,
                              out_w, f1w, f2w, c1w, fpw, out_b);
    k_convert<<<512, 256>>>(perc, tech, Xh, B);

    // G1: seq = X@{Wp|Wt} + (b + out_b)
    k_gemm128<<<dim3(74, 1, 2), NTH, SM_G192>>>(
        Xh, 192, hWp, hWt, 192, bSP, bST, 192, B / 128, B,
        nullptr, seq, nullptr, 192, 0);
    // G2: qkv = X@{Qp|Qt} + bQ
    k_gemm128<<<dim3(74, 3, 2), NTH, SM_G192>>>(
        Xh, 192, hQp, hQt, 576, bQp, bQt, 192, B / 128, B,
        qkv, nullptr, nullptr, 576, 0);
    k_attn<<<1024, 256>>>(qkv, ctx, B);
    // G3: x = LN1(seq + ctx@outW)
    k_ln1<<<dim3(148, 1, 1), NTH, SM_LN>>>(ctx, hOut, seq, ln1g, ln1b,
                                           xf, xh, (2 * B) / 64);
    // G4: h = relu(x@F1 + b1)
    k_gemm128<<<dim3(74, 2, 1), NTH, SM_G192>>>(
        xh, 192, hF1, hF1, 384, f1b, f1b, 192, (2 * B) / 128, B,
        hh, nullptr, nullptr, 384, 1);
    // G5: y2 = x + h@F2 + b2
    k_gemm128<<<dim3(148, 1, 1), NTH, SM_G384>>>(
        hh, 384, hF2, hF2, 192, f2b, f2b, 384, (2 * B) / 128, B,
        nullptr, y2, xf, 192, 0);
    k_lnz<<<1024, 256>>>(y2, ln2g, ln2b, zh, B);
    // heads
    k_cls<<<dim3(148, 1, 1), NTH, SM_LN>>>(zh, hC1, c1b, c2w, c2b, out, B, B / 64);
    k_fp<<<dim3(148, 1, 1), NTH, SM_LN>>>(zh, hFp2, fpb, out, B, B / 64);
}

// round 14
// speedup vs baseline: 1.6247x; 1.1155x over previous
#include <cuda_runtime.h>
#include <cuda_fp16.h>
#include <cstdint>
#include <math.h>

#define NTH 512
#define NB  65536
#define ROWS2 (2 * NB)          // 131072
#define ROWSP 131136            // 683 * 192 (padded for MT=192)

// ---------------- device scratch (static, zero-initialized) ----------------
__device__ __half g_Xh [(size_t)ROWS2 * 192];
__device__ __half g_qkv[(size_t)ROWS2 * 576];
__device__ __half g_ctx[(size_t)ROWS2 * 192];
__device__ float  g_xf [(size_t)ROWS2 * 192];   // x after LN1 (fp32, interleaved)
__device__ __half g_xh [(size_t)ROWSP * 192];   // x after LN1 (fp16, interleaved+pad)
__device__ __half g_hh [(size_t)ROWSP * 384];   // FFN hidden (interleaved+pad)
__device__ __half g_zh [(size_t)NB * 192];      // pooled z fp16

// ---------------- fp16 k-major weights ----------------
__device__ __align__(16) __half g_hQp[192 * 576];   // (in_w @ Wp)^T
__device__ __align__(16) __half g_hQt[192 * 576];
__device__ __align__(16) __half g_hOP[384 * 192];   // [out_w ; Wp] stacked k-major
__device__ __align__(16) __half g_hOT[384 * 192];
__device__ __align__(16) __half g_hF1[192 * 384];
__device__ __align__(16) __half g_hF2[384 * 192];
__device__ __align__(16) __half g_hC1[192 * 192];
__device__ __align__(16) __half g_hFp2[192 * 192];
__device__ float g_bQp[576], g_bQt[576];
__device__ float g_bSeqP[192], g_bSeqT[192];

__device__ __forceinline__ void cp_async16(uint32_t dst, const void* src) {
    asm volatile("cp.async.cg.shared.global [%0], [%1], 16;\n" :: "r"(dst), "l"(src));
}

__global__ void prep_kernel(const float* Wp, const float* Wt, const float* in_w,
                            const float* in_b, const float* bp, const float* bt,
                            const float* out_w, const float* f1w, const float* f2w,
                            const float* c1w, const float* fpw, const float* out_b) {
    const int t0 = blockIdx.x * blockDim.x + threadIdx.x;
    const int nthr = gridDim.x * blockDim.x;
    {
        const float* srcs[3] = {f1w, f2w, c1w};
        __half* dsts[3] = {g_hF1, g_hF2, g_hC1};
        const int Rs[3] = {384, 192, 192};
        const int Cs[3] = {192, 384, 192};
#pragma unroll 1
        for (int m = 0; m < 3; ++m) {
            int n = Rs[m] * Cs[m];
            for (int d = t0; d < n; d += nthr) {
                int k = d / Rs[m], j = d % Rs[m];
                dsts[m][d] = __float2half(srcs[m][j * Cs[m] + k]);
            }
        }
    }
    for (int d = t0; d < 192 * 192; d += nthr) {
        int k = d / 192, j = d % 192;
        g_hFp2[d] = __float2half(j < 128 ? fpw[j * 192 + k] : 0.f);
    }
    // stacked [out_w ; W_{p,t}] k-major: rows 0..191 out_w, rows 192..383 proj
    for (int d = t0; d < 384 * 192; d += nthr) {
        int k = d / 192, j = d % 192;
        if (k < 192) {
            __half v = __float2half(out_w[j * 192 + k]);
            g_hOP[d] = v;
            g_hOT[d] = v;
        } else {
            g_hOP[d] = __float2half(Wp[j * 192 + (k - 192)]);
            g_hOT[d] = __float2half(Wt[j * 192 + (k - 192)]);
        }
    }
    for (int d = t0; d < 192 * 576; d += nthr) {
        int k = d / 576, j = d % 576;
        float sp = 0.f, st = 0.f;
        const float* iw = in_w + (size_t)j * 192;
#pragma unroll 4
        for (int m = 0; m < 192; ++m) {
            float w = iw[m];
            sp += w * Wp[m * 192 + k];
            st += w * Wt[m * 192 + k];
        }
        g_hQp[d] = __float2half(sp);
        g_hQt[d] = __float2half(st);
    }
    for (int j = t0; j < 576; j += nthr) {
        float sp = in_b[j], st = in_b[j];
        const float* iw = in_w + (size_t)j * 192;
#pragma unroll 4
        for (int m = 0; m < 192; ++m) {
            float w = iw[m];
            sp += w * bp[m];
            st += w * bt[m];
        }
        g_bQp[j] = sp;
        g_bQt[j] = st;
    }
    for (int j = t0; j < 192; j += nthr) {
        g_bSeqP[j] = bp[j] + out_b[j];
        g_bSeqT[j] = bt[j] + out_b[j];
    }
}

#define MMA16(dd, a0, a1, a2, a3, b0, b1)                                        \
    asm volatile("mma.sync.aligned.m16n8k16.row.col.f32.f16.f16.f32 "            \
                 "{%0,%1,%2,%3}, {%4,%5,%6,%7}, {%8,%9}, {%0,%1,%2,%3};"         \
                 : "+f"(dd[0]), "+f"(dd[1]), "+f"(dd[2]), "+f"(dd[3])            \
                 : "r"(a0), "r"(a1), "r"(a2), "r"(a3), "r"(b0), "r"(b1))

// ---------------- streaming GEMM mainloop ----------------
// W slice [K][192] resident in smem; A streamed in [MT][64] chunks from A1
// (chunks < nk1) then A2, 4-slot ring, prefetch 2 ahead, one barrier/chunk.
template<int MT, class Epi>
__device__ __forceinline__ void run_gemm(
    const __half* __restrict__ A1, int lda1,
    const __half* __restrict__ A2, int lda2, int nk1,
    int rowbase, const __half* __restrict__ W, int ldw, int jw0,
    int K, int mtiles, Epi epi)
{
    extern __shared__ float smemf[];
    __half* sA = (__half*)smemf;
    __half* sW = sA + 4 * MT * 72;
    constexpr int RM = MT / 64;
    const int tid = threadIdx.x;
    const int wid = tid >> 5, lane = tid & 31;
    const int mw = wid & 3, nw = wid >> 2;
    const int r0 = mw * (MT / 4);
    const int nk = K >> 6;
    const int bx = blockIdx.x, gxs = gridDim.x;

    const uint32_t sAu = (uint32_t)__cvta_generic_to_shared(sA);
    const uint32_t sWu = (uint32_t)__cvta_generic_to_shared(sW);

    {
        int nseg = K * 24;
        for (int s = tid; s < nseg; s += NTH) {
            int row = s / 24, col = (s % 24) << 3;
            cp_async16(sWu + (uint32_t)((row * 200 + col) * 2),
                       W + (size_t)row * ldw + jw0 + col);
        }
        asm volatile("cp.async.commit_group;\n" ::: "memory");
    }

    const int nIter = (mtiles > bx) ? ((mtiles - bx + gxs - 1) / gxs) : 0;
    const int Q = nIter * nk;

    auto issueA = [&](int q) {
        int it = q / nk, kc = q - it * nk;
        int mt = bx + it * gxs;
        const __half* src;
        if (kc < nk1)
            src = A1 + (size_t)(rowbase + mt * MT) * lda1 + kc * 64;
        else
            src = A2 + (size_t)(rowbase + mt * MT) * lda2 + (kc - nk1) * 64;
        int lda = (kc < nk1) ? lda1 : lda2;
        uint32_t dst = sAu + (uint32_t)((q & 3) * MT * 72 * 2);
#pragma unroll
        for (int i = 0; i < (MT * 8) / NTH; ++i) {
            int s = tid + i * NTH;
            int row = s >> 3, cs = (s & 7) << 3;
            cp_async16(dst + (uint32_t)((row * 72 + cs) * 2),
                       src + (size_t)row * lda + cs);
        }
        asm volatile("cp.async.commit_group;\n" ::: "memory");
    };
    if (Q > 0) issueA(0);
    if (Q > 1) issueA(1);

    float d[RM][6][4];
#pragma unroll
    for (int rm = 0; rm < RM; ++rm)
#pragma unroll
        for (int nt = 0; nt < 6; ++nt)
            d[rm][nt][0] = d[rm][nt][1] = d[rm][nt][2] = d[rm][nt][3] = 0.f;

    const int bk = (lane & 7) | (lane & 8);
    const int bn = nw * 48 + ((lane >> 4) << 3);
    const uint32_t aoff = (uint32_t)(((r0 + (lane & 15)) * 72 + ((lane >> 4) << 3)) * 2);

    int kc = 0, mtc = bx;
    for (int q = 0; q < Q; ++q) {
        if (q + 2 < Q) {
            issueA(q + 2);
            asm volatile("cp.async.wait_group 2;\n" ::: "memory");
        } else if (q + 1 < Q) {
            asm volatile("cp.async.wait_group 1;\n" ::: "memory");
        } else {
            asm volatile("cp.async.wait_group 0;\n" ::: "memory");
        }
        __syncthreads();
        uint32_t aAddr0 = sAu + (uint32_t)((q & 3) * MT * 72 * 2) + aoff;
#pragma unroll
        for (int ks = 0; ks < 4; ++ks) {
            uint32_t af[RM][4];
#pragma unroll
            for (int rm = 0; rm < RM; ++rm)
                asm volatile("ldmatrix.sync.aligned.m8n8.x4.shared.b16 {%0,%1,%2,%3}, [%4];"
                             : "=r"(af[rm][0]), "=r"(af[rm][1]),
                               "=r"(af[rm][2]), "=r"(af[rm][3])
                             : "r"(aAddr0 + (uint32_t)((rm * 16 * 72 + ks * 16) * 2)));
            uint32_t bRow = sWu + (uint32_t)(((kc * 64 + ks * 16 + bk) * 200 + bn) * 2);
#pragma unroll
            for (int gi = 0; gi < 3; ++gi) {
                uint32_t b0, b1, b2, b3;
                asm volatile("ldmatrix.sync.aligned.m8n8.x4.trans.shared.b16 "
                             "{%0,%1,%2,%3}, [%4];"
                             : "=r"(b0), "=r"(b1), "=r"(b2), "=r"(b3)
                             : "r"(bRow + (uint32_t)(gi * 16 * 2)));
#pragma unroll
                for (int rm = 0; rm < RM; ++rm) {
                    MMA16(d[rm][gi * 2],     af[rm][0], af[rm][1], af[rm][2], af[rm][3], b0, b1);
                    MMA16(d[rm][gi * 2 + 1], af[rm][0], af[rm][1], af[rm][2], af[rm][3], b2, b3);
                }
            }
        }
        if (++kc == nk) {
            kc = 0;
            epi(mtc, d);
            mtc += gxs;
#pragma unroll
            for (int rm = 0; rm < RM; ++rm)
#pragma unroll
                for (int nt = 0; nt < 6; ++nt)
                    d[rm][nt][0] = d[rm][nt][1] = d[rm][nt][2] = d[rm][nt][3] = 0.f;
        }
    }
}

// ---------------- plain GEMM (G2 qkv, G4 ffn1) ----------------
template<int MT>
__global__ __launch_bounds__(NTH, 1)
void k_gemm(const __half* __restrict__ A, int lda,
            const __half* __restrict__ W0, const __half* __restrict__ W1,
            int ldw, const float* __restrict__ bias0,
            const float* __restrict__ bias1,
            int K, int mtiles, int B,
            __half* __restrict__ outH, int ldo, int relu)
{
    const int zz = blockIdx.z;
    const __half* W = zz ? W1 : W0;
    const float* bias = zz ? bias1 : bias0;
    const int jw0 = blockIdx.y * 192;
    const int rowbase = zz * B;
    const int tid = threadIdx.x;
    const int wid = tid >> 5, lane = tid & 31;
    const int mw = wid & 3, nw = wid >> 2;
    const int g = lane >> 2, c = lane & 3;
    const int r0 = mw * (MT / 4);

    run_gemm<MT>(A, lda, A, lda, K >> 6, rowbase, W, ldw, jw0, K, mtiles,
        [&](int mt, auto& d) {
#pragma unroll
            for (int rm = 0; rm < MT / 64; ++rm) {
                size_t rA = (size_t)rowbase + (size_t)mt * MT + r0 + rm * 16 + g;
                size_t rB = rA + 8;
#pragma unroll
                for (int nt = 0; nt < 6; ++nt) {
                    int jc = nw * 48 + nt * 8 + 2 * c;
                    float bx = bias[jw0 + jc], by = bias[jw0 + jc + 1];
                    float2 v0 = make_float2(d[rm][nt][0] + bx, d[rm][nt][1] + by);
                    float2 v1 = make_float2(d[rm][nt][2] + bx, d[rm][nt][3] + by);
                    if (relu) {
                        v0.x = fmaxf(v0.x, 0.f); v0.y = fmaxf(v0.y, 0.f);
                        v1.x = fmaxf(v1.x, 0.f); v1.y = fmaxf(v1.y, 0.f);
                    }
                    *(__half2*)&outH[rA * ldo + jw0 + jc] = __floats2half2_rn(v0.x, v0.y);
                    *(__half2*)&outH[rB * ldo + jw0 + jc] = __floats2half2_rn(v1.x, v1.y);
                }
            }
        });
}

// ---------------- fused: [ctx | X] @ [out_w ; W_z] + b -> LN1 -> xf/xh ------
// red region offset: (4*128*72 + 384*200) halves = 227328 B -> float idx 56832
__global__ __launch_bounds__(NTH, 1)
void k_ln1f(const __half* __restrict__ ctx, const __half* __restrict__ X,
            const __half* __restrict__ Wc0, const __half* __restrict__ Wc1,
            const float* __restrict__ bias0, const float* __restrict__ bias1,
            const float* __restrict__ lng, const float* __restrict__ lnb,
            float* __restrict__ xf, __half* __restrict__ xh,
            int mtiles, int B)
{
    extern __shared__ float smemf[];
    float2* red = (float2*)(smemf + 56832);   // [128][4]
    const int zz = blockIdx.z;
    const __half* W = zz ? Wc1 : Wc0;
    const float* bias = zz ? bias1 : bias0;
    const int rowbase = zz * B;
    const int tid = threadIdx.x;
    const int wid = tid >> 5, lane = tid & 31;
    const int mw = wid & 3, nw = wid >> 2;
    const int g = lane >> 2, c = lane & 3;
    const int r0 = mw * 32;

    run_gemm<128>(ctx, 192, X, 192, 3, rowbase, W, 192, 0, 384, mtiles,
        [&](int mt, auto& d) {
            // bias
#pragma unroll
            for (int rm = 0; rm < 2; ++rm)
#pragma unroll
                for (int nt = 0; nt < 6; ++nt) {
                    int jc = nw * 48 + nt * 8 + 2 * c;
                    float bx = bias[jc], by = bias[jc + 1];
                    d[rm][nt][0] += bx; d[rm][nt][1] += by;
                    d[rm][nt][2] += bx; d[rm][nt][3] += by;
                }
            // row stats
#pragma unroll
            for (int rm = 0; rm < 2; ++rm)
#pragma unroll
                for (int hf = 0; hf < 2; ++hf) {
                    float s = 0.f, qq = 0.f;
#pragma unroll
                    for (int nt = 0; nt < 6; ++nt) {
                        float v0 = d[rm][nt][2 * hf], v1 = d[rm][nt][2 * hf + 1];
                        s += v0 + v1; qq += v0 * v0 + v1 * v1;
                    }
                    s += __shfl_xor_sync(0xffffffffu, s, 1);
                    s += __shfl_xor_sync(0xffffffffu, s, 2);
                    qq += __shfl_xor_sync(0xffffffffu, qq, 1);
                    qq += __shfl_xor_sync(0xffffffffu, qq, 2);
                    if (c == 0) {
                        int row = r0 + rm * 16 + hf * 8 + g;
                        red[row * 4 + nw] = make_float2(s, qq);
                    }
                }
            __syncthreads();
#pragma unroll
            for (int rm = 0; rm < 2; ++rm)
#pragma unroll
                for (int hf = 0; hf < 2; ++hf) {
                    int row = r0 + rm * 16 + hf * 8 + g;
                    float S = 0.f, QQ = 0.f;
#pragma unroll
                    for (int w = 0; w < 4; ++w) {
                        float2 t = red[row * 4 + w];
                        S += t.x; QQ += t.y;
                    }
                    float mu = S * (1.f / 192.f);
                    float rstd = rsqrtf(QQ * (1.f / 192.f) - mu * mu + 1e-5f);
                    size_t gr = 2u * ((size_t)mt * 128 + row) + zz;
#pragma unroll
                    for (int nt = 0; nt < 6; ++nt) {
                        int jc = nw * 48 + nt * 8 + 2 * c;
                        float y0 = (d[rm][nt][2 * hf] - mu) * rstd * lng[jc] + lnb[jc];
                        float y1 = (d[rm][nt][2 * hf + 1] - mu) * rstd * lng[jc + 1] + lnb[jc + 1];
                        *(float2*)&xf[gr * 192 + jc] = make_float2(y0, y1);
                        *(__half2*)&xh[gr * 192 + jc] = __floats2half2_rn(y0, y1);
                    }
                }
        });
}

// ---------------- fused: hh @ F2 + b + xf -> LN2 -> pool -> zh -------------
__global__ __launch_bounds__(NTH, 1)
void k_ffn2(const __half* __restrict__ hh, const __half* __restrict__ Wf2,
            const float* __restrict__ f2b, const float* __restrict__ xf,
            const float* __restrict__ lng, const float* __restrict__ lnb,
            __half* __restrict__ zh, int mtiles)
{
    extern __shared__ float smemf[];
    float2* red = (float2*)(smemf + 56832);
    const int tid = threadIdx.x;
    const int wid = tid >> 5, lane = tid & 31;
    const int mw = wid & 3, nw = wid >> 2;
    const int g = lane >> 2, c = lane & 3;
    const int r0 = mw * 32;

    run_gemm<128>(hh, 384, hh, 384, 6, 0, Wf2, 192, 0, 384, mtiles,
        [&](int mt, auto& d) {
            // bias + residual
#pragma unroll
            for (int rm = 0; rm < 2; ++rm) {
                size_t rA = (size_t)mt * 128 + r0 + rm * 16 + g;
                size_t rB = rA + 8;
#pragma unroll
                for (int nt = 0; nt < 6; ++nt) {
                    int jc = nw * 48 + nt * 8 + 2 * c;
                    float bx = f2b[jc], by = f2b[jc + 1];
                    float2 s0 = *(const float2*)&xf[rA * 192 + jc];
                    float2 s1 = *(const float2*)&xf[rB * 192 + jc];
                    d[rm][nt][0] += bx + s0.x; d[rm][nt][1] += by + s0.y;
                    d[rm][nt][2] += bx + s1.x; d[rm][nt][3] += by + s1.y;
                }
            }
            // stats
#pragma unroll
            for (int rm = 0; rm < 2; ++rm)
#pragma unroll
                for (int hf = 0; hf < 2; ++hf) {
                    float s = 0.f, qq = 0.f;
#pragma unroll
                    for (int nt = 0; nt < 6; ++nt) {
                        float v0 = d[rm][nt][2 * hf], v1 = d[rm][nt][2 * hf + 1];
                        s += v0 + v1; qq += v0 * v0 + v1 * v1;
                    }
                    s += __shfl_xor_sync(0xffffffffu, s, 1);
                    s += __shfl_xor_sync(0xffffffffu, s, 2);
                    qq += __shfl_xor_sync(0xffffffffu, qq, 1);
                    qq += __shfl_xor_sync(0xffffffffu, qq, 2);
                    if (c == 0) {
                        int row = r0 + rm * 16 + hf * 8 + g;
                        red[row * 4 + nw] = make_float2(s, qq);
                    }
                }
            __syncthreads();
#pragma unroll
            for (int rm = 0; rm < 2; ++rm)
#pragma unroll
                for (int hf = 0; hf < 2; ++hf) {
                    int row = r0 + rm * 16 + hf * 8 + g;
                    float S = 0.f, QQ = 0.f;
#pragma unroll
                    for (int w = 0; w < 4; ++w) {
                        float2 t = red[row * 4 + w];
                        S += t.x; QQ += t.y;
                    }
                    float mu = S * (1.f / 192.f);
                    float rstd = rsqrtf(QQ * (1.f / 192.f) - mu * mu + 1e-5f);
#pragma unroll
                    for (int nt = 0; nt < 6; ++nt) {
                        int jc = nw * 48 + nt * 8 + 2 * c;
                        float y0 = (d[rm][nt][2 * hf] - mu) * rstd * lng[jc] + lnb[jc];
                        float y1 = (d[rm][nt][2 * hf + 1] - mu) * rstd * lng[jc + 1] + lnb[jc + 1];
                        float p0 = __shfl_xor_sync(0xffffffffu, y0, 4);
                        float p1 = __shfl_xor_sync(0xffffffffu, y1, 4);
                        if (!(g & 1)) {
                            size_t e = ((size_t)mt * 128 + row) >> 1;
                            *(__half2*)&zh[e * 192 + jc] =
                                __floats2half2_rn(0.5f * (y0 + p0), 0.5f * (y1 + p1));
                        }
                    }
                }
        });
}

#define STAGEF (smemf + 28416)

// ---------------- cls head (M64 stage version) ----------------
__global__ __launch_bounds__(NTH, 1)
void k_cls(const __half* __restrict__ zh, const __half* __restrict__ Wc1,
           const float* __restrict__ c1b, const float* __restrict__ c2w,
           const float* __restrict__ c2b, float* __restrict__ outp,
           int B, int mtiles)
{
    extern __shared__ float smemf[];
    float* stage = STAGEF;
    const int tid = threadIdx.x;
    const int wid = tid >> 5, lane = tid & 31;
    const int mw = wid & 3, nw = wid >> 2;
    const int g = lane >> 2, c = lane & 3;
    const int r0 = mw * 16;

    run_gemm<64>(zh, 192, zh, 192, 3, 0, Wc1, 192, 0, 192, mtiles,
        [&](int mt, auto& d) {
            int rA = r0 + g, rB = rA + 8;
#pragma unroll
            for (int nt = 0; nt < 6; ++nt) {
                int jc = nw * 48 + nt * 8 + 2 * c;
                float bx = c1b[jc], by = c1b[jc + 1];
                stage[rA * 196 + jc]     = fmaxf(d[0][nt][0] + bx, 0.f);
                stage[rA * 196 + jc + 1] = fmaxf(d[0][nt][1] + by, 0.f);
                stage[rB * 196 + jc]     = fmaxf(d[0][nt][2] + bx, 0.f);
                stage[rB * 196 + jc + 1] = fmaxf(d[0][nt][3] + by, 0.f);
            }
            __syncthreads();
            if (tid < 192) {
                int row = tid / 3, cls = tid - row * 3;
                float s = c2b[cls];
                const float* w = c2w + cls * 192;
                const float* x = stage + row * 196;
#pragma unroll 8
                for (int kk = 0; kk < 192; ++kk) s += x[kk] * w[kk];
                outp[(size_t)cls * B + (size_t)mt * 64 + row] =
                    1.f / (1.f + __expf(-s));
            }
            __syncthreads();
        });
}

// ---------------- fp head (M64 stage version) ----------------
__global__ __launch_bounds__(NTH, 1)
void k_fp(const __half* __restrict__ zh, const __half* __restrict__ Wfp,
          const float* __restrict__ fpb, float* __restrict__ outp,
          int B, int mtiles)
{
    extern __shared__ float smemf[];
    float* stage = STAGEF;
    const int tid = threadIdx.x;
    const int wid = tid >> 5, lane = tid & 31;
    const int mw = wid & 3, nw = wid >> 2;
    const int g = lane >> 2, c = lane & 3;
    const int r0 = mw * 16;

    run_gemm<64>(zh, 192, zh, 192, 3, 0, Wfp, 192, 0, 192, mtiles,
        [&](int mt, auto& d) {
            int rA = r0 + g, rB = rA + 8;
#pragma unroll
            for (int nt = 0; nt < 6; ++nt) {
                int jc = nw * 48 + nt * 8 + 2 * c;
                float bx = (jc < 128) ? fpb[jc] : 0.f;
                float by = (jc + 1 < 128) ? fpb[jc + 1] : 0.f;
                stage[rA * 196 + jc]     = d[0][nt][0] + bx;
                stage[rA * 196 + jc + 1] = d[0][nt][1] + by;
                stage[rB * 196 + jc]     = d[0][nt][2] + bx;
                stage[rB * 196 + jc + 1] = d[0][nt][3] + by;
            }
            __syncthreads();
#pragma unroll
            for (int t = 0; t < 4; ++t) {
                int row = wid * 4 + t;
                float v[4], ss = 0.f;
#pragma unroll
                for (int e = 0; e < 4; ++e) {
                    v[e] = stage[row * 196 + lane + e * 32];
                    ss += v[e] * v[e];
                }
#pragma unroll
                for (int o = 16; o; o >>= 1) ss += __shfl_xor_sync(0xffffffffu, ss, o);
                float inv = 1.f / fmaxf(sqrtf(ss), 1e-12f);
                size_t grow = (size_t)mt * 64 + row;
#pragma unroll
                for (int e = 0; e < 4; ++e)
                    outp[(size_t)3 * B + grow * 128 + lane + e * 32] = v[e] * inv;
            }
            __syncthreads();
        });
}

// ---------------- small kernels ----------------
__global__ void k_convert(const float* __restrict__ perc,
                          const float* __restrict__ tech,
                          __half* __restrict__ Xh, int B) {
    int n4 = B * 48;
    for (int idx = blockIdx.x * blockDim.x + threadIdx.x; idx < n4;
         idx += gridDim.x * blockDim.x) {
        int e = idx / 48, c4 = (idx % 48) * 4;
        float4 vp = *(const float4*)&perc[(size_t)e * 192 + c4];
        float4 vt = *(const float4*)&tech[(size_t)e * 192 + c4];
        *(__half2*)&Xh[(size_t)e * 192 + c4]     = __floats2half2_rn(vp.x, vp.y);
        *(__half2*)&Xh[(size_t)e * 192 + c4 + 2] = __floats2half2_rn(vp.z, vp.w);
        *(__half2*)&Xh[((size_t)B + e) * 192 + c4]     = __floats2half2_rn(vt.x, vt.y);
        *(__half2*)&Xh[((size_t)B + e) * 192 + c4 + 2] = __floats2half2_rn(vt.z, vt.w);
    }
}

__global__ void k_attn(const __half* __restrict__ qkv, __half* __restrict__ ctx,
                       int B) {
    int gw = (blockIdx.x * blockDim.x + threadIdx.x) >> 5;
    int lane = threadIdx.x & 31;
    int nwarps = (gridDim.x * blockDim.x) >> 5;
    for (int e = gw; e < B; e += nwarps) {
        const __half2* r0 = (const __half2*)(qkv + (size_t)e * 576);
        const __half2* r1 = (const __half2*)(qkv + ((size_t)B + e) * 576);
        __half2* c0 = (__half2*)(ctx + (size_t)e * 192);
        __half2* c1 = (__half2*)(ctx + ((size_t)B + e) * 192);
#pragma unroll
        for (int h = 0; h < 3; ++h) {
            int o = h * 32 + lane;
            float2 q0 = __half22float2(r0[o]),      q1 = __half22float2(r1[o]);
            float2 k0 = __half22float2(r0[96 + o]), k1 = __half22float2(r1[96 + o]);
            float d00 = q0.x * k0.x + q0.y * k0.y;
            float d01 = q0.x * k1.x + q0.y * k1.y;
            float d10 = q1.x * k0.x + q1.y * k0.y;
            float d11 = q1.x * k1.x + q1.y * k1.y;
#pragma unroll
            for (int s = 16; s; s >>= 1) {
                d00 += __shfl_xor_sync(0xffffffffu, d00, s);
                d01 += __shfl_xor_sync(0xffffffffu, d01, s);
                d10 += __shfl_xor_sync(0xffffffffu, d10, s);
                d11 += __shfl_xor_sync(0xffffffffu, d11, s);
            }
            const float sc = 0.125f;
            d00 *= sc; d01 *= sc; d10 *= sc; d11 *= sc;
            float m0 = fmaxf(d00, d01), m1 = fmaxf(d10, d11);
            float e00 = __expf(d00 - m0), e01 = __expf(d01 - m0);
            float e10 = __expf(d10 - m1), e11 = __expf(d11 - m1);
            float i0 = 1.f / (e00 + e01), i1 = 1.f / (e10 + e11);
            float a00 = e00 * i0, a01 = e01 * i0;
            float a10 = e10 * i1, a11 = e11 * i1;
            float2 v0 = __half22float2(r0[192 + o]);
            float2 v1 = __half22float2(r1[192 + o]);
            c0[o] = __floats2half2_rn(a00 * v0.x + a01 * v1.x,
                                      a00 * v0.y + a01 * v1.y);
            c1[o] = __floats2half2_rn(a10 * v0.x + a11 * v1.x,
                                      a10 * v0.y + a11 * v1.y);
        }
    }
}

// ---------------- host ----------------
#define SM_G128 150528   // 4*128*72*2 + 192*200*2
#define SM_G192 187392   // 4*192*72*2 + 192*200*2
#define SM_FUSE 231424   // 4*128*72*2 + 384*200*2 + 4096
#define SM_HEAD 163840   // 4*64*72*2 + 192*200*2 + 64*196*4

extern "C" void kernel_launch(void* const* d_in, const int* in_sizes, int n_in,
                              void* d_out, int out_size) {
    const float* perc = (const float*)d_in[0];
    const float* tech = (const float*)d_in[1];
    const float* Wp   = (const float*)d_in[2];
    const float* bp   = (const float*)d_in[3];
    const float* Wt   = (const float*)d_in[4];
    const float* bt   = (const float*)d_in[5];
    const float* in_w = (const float*)d_in[6];
    const float* in_b = (const float*)d_in[7];
    const float* out_w= (const float*)d_in[8];
    const float* out_b= (const float*)d_in[9];
    const float* f1w  = (const float*)d_in[10];
    const float* f1b  = (const float*)d_in[11];
    const float* f2w  = (const float*)d_in[12];
    const float* f2b  = (const float*)d_in[13];
    const float* ln1g = (const float*)d_in[14];
    const float* ln1b = (const float*)d_in[15];
    const float* ln2g = (const float*)d_in[16];
    const float* ln2b = (const float*)d_in[17];
    const float* c1w  = (const float*)d_in[18];
    const float* c1b  = (const float*)d_in[19];
    const float* c2w  = (const float*)d_in[20];
    const float* c2b  = (const float*)d_in[21];
    const float* fpw  = (const float*)d_in[22];
    const float* fpb  = (const float*)d_in[23];
    float* out = (float*)d_out;
    const int B = in_sizes[0] / 192;

    static int inited = 0;
    if (!inited) {
        inited = 1;
        cudaFuncSetAttribute(k_gemm<128>, cudaFuncAttributeMaxDynamicSharedMemorySize, SM_G128);
        cudaFuncSetAttribute(k_gemm<192>, cudaFuncAttributeMaxDynamicSharedMemorySize, SM_G192);
        cudaFuncSetAttribute(k_ln1f, cudaFuncAttributeMaxDynamicSharedMemorySize, SM_FUSE);
        cudaFuncSetAttribute(k_ffn2, cudaFuncAttributeMaxDynamicSharedMemorySize, SM_FUSE);
        cudaFuncSetAttribute(k_cls, cudaFuncAttributeMaxDynamicSharedMemorySize, SM_HEAD);
        cudaFuncSetAttribute(k_fp,  cudaFuncAttributeMaxDynamicSharedMemorySize, SM_HEAD);
    }

    __half *Xh, *qkv, *ctx, *xh, *hh, *zh;
    float *xf;
    cudaGetSymbolAddress((void**)&Xh,  g_Xh);
    cudaGetSymbolAddress((void**)&qkv, g_qkv);
    cudaGetSymbolAddress((void**)&ctx, g_ctx);
    cudaGetSymbolAddress((void**)&xh,  g_xh);
    cudaGetSymbolAddress((void**)&hh,  g_hh);
    cudaGetSymbolAddress((void**)&zh,  g_zh);
    cudaGetSymbolAddress((void**)&xf,  g_xf);

    __half *hQp, *hQt, *hOP, *hOT, *hF1, *hF2, *hC1, *hFp2;
    float *bQp, *bQt, *bSP, *bST;
    cudaGetSymbolAddress((void**)&hQp, g_hQp);
    cudaGetSymbolAddress((void**)&hQt, g_hQt);
    cudaGetSymbolAddress((void**)&hOP, g_hOP);
    cudaGetSymbolAddress((void**)&hOT, g_hOT);
    cudaGetSymbolAddress((void**)&hF1, g_hF1);
    cudaGetSymbolAddress((void**)&hF2, g_hF2);
    cudaGetSymbolAddress((void**)&hC1, g_hC1);
    cudaGetSymbolAddress((void**)&hFp2, g_hFp2);
    cudaGetSymbolAddress((void**)&bQp, g_bQp);
    cudaGetSymbolAddress((void**)&bQt, g_bQt);
    cudaGetSymbolAddress((void**)&bSP, g_bSeqP);
    cudaGetSymbolAddress((void**)&bST, g_bSeqT);

    prep_kernel<<<512, 256>>>(Wp, Wt, in_w, in_b, bp, bt,
                              out_w, f1w, f2w, c1w, fpw, out_b);
    k_convert<<<512, 256>>>(perc, tech, Xh, B);

    // qkv = X@{Qp|Qt} + bQ   (grouped rows)
    k_gemm<128><<<dim3(74, 3, 2), NTH, SM_G128>>>(
        Xh, 192, hQp, hQt, 576, bQp, bQt, 192, B / 128, B, qkv, 576, 0);
    k_attn<<<1024, 256>>>(qkv, ctx, B);
    // x = LN1(ctx@outW + X@W_z + b)  -> interleaved xf/xh
    k_ln1f<<<dim3(74, 1, 2), NTH, SM_FUSE>>>(
        ctx, Xh, hOP, hOT, bSP, bST, ln1g, ln1b, xf, xh, B / 128, B);
    // h = relu(x@F1 + b1)  (interleaved, padded tiles)
    k_gemm<192><<<dim3(74, 2, 1), NTH, SM_G192>>>(
        xh, 192, hF1, hF1, 384, f1b, f1b, 192, (ROWS2 + 191) / 192, B, hh, 384, 1);
    // z = pool(LN2(x + h@F2 + b2))
    k_ffn2<<<dim3(148, 1, 1), NTH, SM_FUSE>>>(
        hh, hF2, f2b, xf, ln2g, ln2b, zh, ROWS2 / 128);
    // heads
    k_cls<<<dim3(148, 1, 1), NTH, SM_HEAD>>>(zh, hC1, c1b, c2w, c2b, out, B, B / 64);
    k_fp<<<dim3(148, 1, 1), NTH, SM_HEAD>>>(zh, hFp2, fpb, out, B, B / 64);
}